// round 15
// baseline (speedup 1.0000x reference)
#include <cuda_runtime.h>
#include <cuda_fp16.h>
#include <math.h>
#include <stdint.h>

// ---------------- problem dims (fixed by setup_inputs) ----------------
#define NA    100000      // atoms
#define MM    12          // neighbors per atom
#define ORIG  92          // input atom feature dim
#define NBRF  41          // neighbor (bond) feature dim
#define FF    64          // hidden feature dim
#define HH    128         // fc hidden
#define BB    2000        // crystals
#define NCONV 3
#define NM    (NA*MM)     // 1.2M edge rows
#define TWOF  (2*FF)      // 128
#define WF_ROWS (2*FF + NBRF)         // 169
#define WF_STRIDE (WF_ROWS * TWOF)    // 169*128 per layer

#define TILE_E  64                    // edges per GEMM tile
#define NTILES  (NM / TILE_E)         // 18750 exactly
#define KPAD    48                    // K padded to mult of 8
#define KSTEPS  6
#define NFS     49                    // padded k-stride for A staging
#define CSS     132                   // padded col-stride for C staging (mult of 4)
#define NATILE  7                     // max atoms spanned by a 64-edge tile
#define KG_GRID 740                   // 148 SMs * 5

// ---------------- scratch (device globals; no allocation) -------------
__device__ float  g_h[NA * FF];                 // 25.6 MB
__device__ float  g_A[NA * TWOF];               // 51.2 MB  h @ Wf_self
__device__ float  g_P[NA * TWOF];               // 51.2 MB  h @ Wf_nbr
__device__ __half g_Gh[NM * TWOF];              // 307 MB   fp16 gated pre-BN
__device__ __align__(16) float g_summed[NA * FF];  // 25.6 MB
__device__ double g_stat1[2 * TWOF];            // sum / sumsq (128 cols)
__device__ double g_stat2[2 * FF];              // sum / sumsq (64 cols)
__device__ __align__(16) float g_bn1[2 * TWOF]; // scale(128), shift(128)
__device__ float  g_bn2[2 * FF];                // scale(64), shift(64)
__device__ float  g_pool[BB * FF];
__device__ float  g_cnt[BB];

// ---------------- helpers ----------------
__device__ __forceinline__ float softplusf_(float x) {
    return fmaxf(x, 0.f) + __logf(1.f + __expf(-fabsf(x)));
}
__device__ __forceinline__ float sigmoidf_(float x) {
    return 1.f / (1.f + __expf(-x));
}
__device__ __forceinline__ uint32_t f2tf32(float x) {
    uint32_t r;
    asm("cvt.rna.tf32.f32 %0, %1;" : "=r"(r) : "f"(x));
    return r;
}
#define MMA_TF32(c0,c1,c2,c3,a0,a1,a2,a3,b0,b1) \
    asm volatile("mma.sync.aligned.m16n8k8.row.col.f32.tf32.tf32.f32 " \
        "{%0,%1,%2,%3},{%4,%5,%6,%7},{%8,%9},{%0,%1,%2,%3};" \
        : "+f"(c0), "+f"(c1), "+f"(c2), "+f"(c3) \
        : "r"(a0), "r"(a1), "r"(a2), "r"(a3), "r"(b0), "r"(b1))

struct TileCtx {
    int tid, lane, warp, m0, r, cq;
};

// Pack B fragments as uint4 pairs: Wp4[(ks*8 + ntp)*32 + lane] holds the
// b-frags for n-tiles 2*ntp (x,y) and 2*ntp+1 (z,w). One LDS.128 per 2 MMAs.
__device__ __forceinline__ void pack_B(uint4* Wp4, const float* __restrict__ Wf, int tid) {
    for (int i = tid; i < KSTEPS * 8 * 32; i += 128) {
        int ks  = i >> 8;            // /(8*32)
        int rem = i & 255;
        int ntp = rem >> 5;
        int ln  = rem & 31;
        int col0 = (2 * ntp) * 8 + (ln >> 2);
        int col1 = col0 + 8;
        int k0 = ks * 8 + (ln & 3);
        float w0 = (k0     < NBRF) ? __ldg(&Wf[(TWOF + k0    ) * TWOF + col0]) : 0.f;
        float w1 = (k0 + 4 < NBRF) ? __ldg(&Wf[(TWOF + k0 + 4) * TWOF + col0]) : 0.f;
        float w2 = (k0     < NBRF) ? __ldg(&Wf[(TWOF + k0    ) * TWOF + col1]) : 0.f;
        float w3 = (k0 + 4 < NBRF) ? __ldg(&Wf[(TWOF + k0 + 4) * TWOF + col1]) : 0.f;
        Wp4[i] = make_uint4(f2tf32(w0), f2tf32(w1), f2tf32(w2), f2tf32(w3));
    }
}

// Stage NF tile with float4 gmem loads (tile is contiguous: 64*41 floats,
// 16B-aligned since e0*41*4 is a multiple of 16 for e0 mult of 64).
__device__ __forceinline__ void stage_NF(uint32_t* U, const float* __restrict__ nbr_fea,
                                         int e0, int tid) {
    const int NQ = TILE_E * NBRF / 4;   // 656
    for (int i = tid; i < NQ; i += 128) {
        float4 v = __ldg((const float4*)&nbr_fea[(size_t)e0 * NBRF + 4 * i]);
        int base = 4 * i;
        int e = base / NBRF;
        int k = base - e * NBRF;
        float vv[4] = {v.x, v.y, v.z, v.w};
        #pragma unroll
        for (int u = 0; u < 4; u++) {
            U[e * NFS + k] = f2tf32(vv[u]);
            if (++k == NBRF) { k = 0; e++; }
        }
    }
    for (int i = tid; i < TILE_E * (KPAD - NBRF); i += 128) {
        int e = i / (KPAD - NBRF);
        int k = NBRF + (i - e * (KPAD - NBRF));
        U[e * NFS + k] = 0;
    }
}

// stage A rows for the tile's atoms into smem
__device__ __forceinline__ void stage_A(float* As, int n_first, int tid) {
    #pragma unroll
    for (int it = 0; it < NATILE; it++) {
        int n = n_first + it;
        if (n > NA - 1) n = NA - 1;
        As[it * TWOF + tid] = __ldg(&g_A[(size_t)n * TWOF + tid]);
    }
}

__device__ __forceinline__ void run_mma(float acc[16][4], const uint32_t* U,
                                        const uint4* Wp4, const TileCtx& c) {
    #pragma unroll
    for (int nt = 0; nt < 16; nt++)
        #pragma unroll
        for (int i = 0; i < 4; i++) acc[nt][i] = 0.f;
    #pragma unroll
    for (int ks = 0; ks < KSTEPS; ks++) {
        uint32_t a0 = U[(c.m0 + c.r    ) * NFS + ks * 8 + c.cq    ];
        uint32_t a1 = U[(c.m0 + c.r + 8) * NFS + ks * 8 + c.cq    ];
        uint32_t a2 = U[(c.m0 + c.r    ) * NFS + ks * 8 + c.cq + 4];
        uint32_t a3 = U[(c.m0 + c.r + 8) * NFS + ks * 8 + c.cq + 4];
        #pragma unroll
        for (int ntp = 0; ntp < 8; ntp++) {
            uint4 b = Wp4[(ks * 8 + ntp) * 32 + c.lane];
            MMA_TF32(acc[2*ntp  ][0], acc[2*ntp  ][1], acc[2*ntp  ][2], acc[2*ntp  ][3],
                     a0, a1, a2, a3, b.x, b.y);
            MMA_TF32(acc[2*ntp+1][0], acc[2*ntp+1][1], acc[2*ntp+1][2], acc[2*ntp+1][3],
                     a0, a1, a2, a3, b.z, b.w);
        }
    }
}

__device__ __forceinline__ void stage_C(float* Cs, const float acc[16][4],
                                        const TileCtx& c, int h) {
    if ((c.warp >> 1) == h) {
        int rl = c.m0 - h * 32 + c.r;
        #pragma unroll
        for (int nt = 0; nt < 16; nt++) {
            int jc = nt * 8 + 2 * c.cq;
            *(float2*)&Cs[(rl    ) * CSS + jc] = make_float2(acc[nt][0], acc[nt][1]);
            *(float2*)&Cs[(rl + 8) * CSS + jc] = make_float2(acc[nt][2], acc[nt][3]);
        }
    }
}

// ---------------- kernels ----------------

// h = atom_fea @ W_emb + b_emb    [NA,92]@[92,64]
__global__ void k_embed(const float* __restrict__ atom,
                        const float* __restrict__ W,
                        const float* __restrict__ b) {
    __shared__ float sW[ORIG * FF];
    __shared__ float sb[FF];
    __shared__ float sa[ORIG];
    int tid = threadIdx.x;            // 64 threads
    for (int i = tid; i < ORIG * FF; i += 64) sW[i] = W[i];
    if (tid < FF) sb[tid] = b[tid];
    __syncthreads();
    for (int r = 0; r < 64; r++) {
        int row = blockIdx.x * 64 + r;
        if (row >= NA) break;
        __syncthreads();
        for (int i = tid; i < ORIG; i += 64) sa[i] = atom[row * ORIG + i];
        __syncthreads();
        float acc = sb[tid];
        #pragma unroll 4
        for (int k = 0; k < ORIG; k++) acc = fmaf(sa[k], sW[k * FF + tid], acc);
        g_h[row * FF + tid] = acc;
    }
}

// A[n,j] = sum_k h[n,k] * Wf[k,j];  P[n,j] = sum_k h[n,k] * Wf[64+k,j]
__global__ void __launch_bounds__(128) k_AP(const float* __restrict__ Wf) {
    __shared__ float sh[4][FF];
    int j = threadIdx.x;
    int n0 = blockIdx.x * 4;
    for (int i = j; i < 4 * FF; i += 128) {
        int r = i >> 6, k = i & 63;
        sh[r][k] = g_h[(n0 + r) * FF + k];
    }
    __syncthreads();
    float a0 = 0, a1 = 0, a2 = 0, a3 = 0;
    float p0 = 0, p1 = 0, p2 = 0, p3 = 0;
    #pragma unroll
    for (int k = 0; k < FF; k++) {
        float wa = __ldg(&Wf[k * TWOF + j]);
        float wb = __ldg(&Wf[(FF + k) * TWOF + j]);
        a0 = fmaf(sh[0][k], wa, a0); p0 = fmaf(sh[0][k], wb, p0);
        a1 = fmaf(sh[1][k], wa, a1); p1 = fmaf(sh[1][k], wb, p1);
        a2 = fmaf(sh[2][k], wa, a2); p2 = fmaf(sh[2][k], wb, p2);
        a3 = fmaf(sh[3][k], wa, a3); p3 = fmaf(sh[3][k], wb, p3);
    }
    g_A[(n0 + 0) * TWOF + j] = a0;  g_P[(n0 + 0) * TWOF + j] = p0;
    g_A[(n0 + 1) * TWOF + j] = a1;  g_P[(n0 + 1) * TWOF + j] = p1;
    g_A[(n0 + 2) * TWOF + j] = a2;  g_P[(n0 + 2) * TWOF + j] = p2;
    g_A[(n0 + 3) * TWOF + j] = a3;  g_P[(n0 + 3) * TWOF + j] = p3;
}

// zero the stat accumulators only (g_summed is overwritten by k_S2)
__global__ void k_zero() {
    int i = threadIdx.x;
    if (i < 2 * TWOF) g_stat1[i] = 0.0;
    if (i < 2 * FF)   g_stat2[i] = 0.0;
}

// ---------------------------------------------------------------------
// Pass 1: k_G1 — tf32 GEMM + A(smem)/P(float4) gather + bias ->
// column stats (fp32 accum -> fp64 atomic) + fp16 spill of G.
// Epilogue threads: jq = tid&31 (col quad), g = tid>>5 (8-edge subgroup).
// ---------------------------------------------------------------------
__global__ void __launch_bounds__(128, 5) k_G1(const float* __restrict__ nbr_fea,
                                               const int*   __restrict__ idx,
                                               const float* __restrict__ Wf,
                                               const float* __restrict__ bf) {
    __shared__ uint4 Wp4[KSTEPS * 8 * 32];            // 24.0 KB
    __shared__ __align__(16) float Cs[32 * CSS];      // 16.9 KB; aliased by U
    __shared__ __align__(16) float As[NATILE * TWOF]; // 3.5 KB
    __shared__ int sidx[TILE_E];
    uint32_t* U = (uint32_t*)Cs;                      // 3136 <= 32*CSS = 4224

    TileCtx c;
    c.tid = threadIdx.x; c.lane = c.tid & 31; c.warp = c.tid >> 5;
    c.m0 = c.warp * 16; c.r = c.lane >> 2; c.cq = c.lane & 3;
    int tid = c.tid;

    pack_B(Wp4, Wf, tid);

    int jq = tid & 31;           // column quad: cols 4jq..4jq+3
    int g  = tid >> 5;           // edge subgroup (8 edges) within 32-half
    float4 bf4 = __ldg((const float4*)&bf[4 * jq]);

    float ds0 = 0, ds1 = 0, ds2 = 0, ds3 = 0;
    float dq0 = 0, dq1 = 0, dq2 = 0, dq3 = 0;

    for (int t = blockIdx.x; t < NTILES; t += gridDim.x) {
        int e0 = t * TILE_E;
        int n_first = e0 / MM;
        __syncthreads();
        stage_NF(U, nbr_fea, e0, tid);
        stage_A(As, n_first, tid);
        if (tid < TILE_E) sidx[tid] = idx[e0 + tid];
        __syncthreads();

        float acc[16][4];
        run_mma(acc, U, Wp4, c);
        __syncthreads();

        #pragma unroll
        for (int h = 0; h < 2; h++) {
            stage_C(Cs, acc, c, h);
            __syncthreads();
            int eg = e0 + h * 32 + g * 8;
            int n  = eg / MM;
            int rem = eg - n * MM;
            int nl  = n - n_first;
            float ts0 = 0, ts1 = 0, ts2 = 0, ts3 = 0;
            float tq0 = 0, tq1 = 0, tq2 = 0, tq3 = 0;
            #pragma unroll
            for (int i = 0; i < 8; i++) {
                int le = g * 8 + i;
                int nb = sidx[h * 32 + le];
                float4 P = __ldg((const float4*)&g_P[(size_t)nb * TWOF + 4 * jq]);
                float4 A = *(const float4*)&As[nl * TWOF + 4 * jq];
                float4 C = *(const float4*)&Cs[le * CSS + 4 * jq];
                float v0 = C.x + A.x + P.x + bf4.x;
                float v1 = C.y + A.y + P.y + bf4.y;
                float v2 = C.z + A.z + P.z + bf4.z;
                float v3 = C.w + A.w + P.w + bf4.w;
                ts0 += v0; tq0 = fmaf(v0, v0, tq0);
                ts1 += v1; tq1 = fmaf(v1, v1, tq1);
                ts2 += v2; tq2 = fmaf(v2, v2, tq2);
                ts3 += v3; tq3 = fmaf(v3, v3, tq3);
                // fp16 spill (includes bias)
                {
                    __half2 ha = __floats2half2_rn(v0, v1);
                    __half2 hb = __floats2half2_rn(v2, v3);
                    uint2 u;
                    u.x = *reinterpret_cast<unsigned*>(&ha);
                    u.y = *reinterpret_cast<unsigned*>(&hb);
                    *reinterpret_cast<uint2*>(&g_Gh[(size_t)(eg + i) * TWOF + 4 * jq]) = u;
                }
                if (++rem == MM) { rem = 0; nl++; }
            }
            ds0 += ts0; ds1 += ts1; ds2 += ts2; ds3 += ts3;
            dq0 += tq0; dq1 += tq1; dq2 += tq2; dq3 += tq3;
            __syncthreads();
        }
    }

    atomicAdd(&g_stat1[4 * jq + 0], (double)ds0);
    atomicAdd(&g_stat1[4 * jq + 1], (double)ds1);
    atomicAdd(&g_stat1[4 * jq + 2], (double)ds2);
    atomicAdd(&g_stat1[4 * jq + 3], (double)ds3);
    atomicAdd(&g_stat1[TWOF + 4 * jq + 0], (double)dq0);
    atomicAdd(&g_stat1[TWOF + 4 * jq + 1], (double)dq1);
    atomicAdd(&g_stat1[TWOF + 4 * jq + 2], (double)dq2);
    atomicAdd(&g_stat1[TWOF + 4 * jq + 3], (double)dq3);
}

// ---------------------------------------------------------------------
// Pass 2: k_S2 — stream fp16 G, bn1 + sigmoid*softplus, per-atom reduce,
// DIRECT store to g_summed (no atomics). 256 thr = 16 atoms x 16 col-quads.
// ---------------------------------------------------------------------
__global__ void __launch_bounds__(256) k_S2() {
    int tid = threadIdx.x;
    int t = tid & 15;                 // filter col quad: cols 4t..4t+3
    int a = tid >> 4;                 // atom within block (0..15)
    int n = blockIdx.x * 16 + a;      // grid = NA/16 = 6250 exact

    float4 scf = *(const float4*)&g_bn1[4 * t];
    float4 scc = *(const float4*)&g_bn1[FF + 4 * t];
    float4 shf = *(const float4*)&g_bn1[TWOF + 4 * t];
    float4 shc = *(const float4*)&g_bn1[TWOF + FF + 4 * t];

    size_t base = (size_t)n * MM * TWOF;
    float s0 = 0, s1 = 0, s2 = 0, s3 = 0;
    #pragma unroll
    for (int m = 0; m < MM; m++) {
        uint2 uf = __ldg((const uint2*)&g_Gh[base + m * TWOF + 4 * t]);
        uint2 uc = __ldg((const uint2*)&g_Gh[base + m * TWOF + FF + 4 * t]);
        float2 f01 = __half22float2(*reinterpret_cast<__half2*>(&uf.x));
        float2 f23 = __half22float2(*reinterpret_cast<__half2*>(&uf.y));
        float2 c01 = __half22float2(*reinterpret_cast<__half2*>(&uc.x));
        float2 c23 = __half22float2(*reinterpret_cast<__half2*>(&uc.y));
        float xf0 = fmaf(scf.x, f01.x, shf.x);
        float xf1 = fmaf(scf.y, f01.y, shf.y);
        float xf2 = fmaf(scf.z, f23.x, shf.z);
        float xf3 = fmaf(scf.w, f23.y, shf.w);
        float xc0 = fmaf(scc.x, c01.x, shc.x);
        float xc1 = fmaf(scc.y, c01.y, shc.y);
        float xc2 = fmaf(scc.z, c23.x, shc.z);
        float xc3 = fmaf(scc.w, c23.y, shc.w);
        s0 = fmaf(sigmoidf_(xf0), softplusf_(xc0), s0);
        s1 = fmaf(sigmoidf_(xf1), softplusf_(xc1), s1);
        s2 = fmaf(sigmoidf_(xf2), softplusf_(xc2), s2);
        s3 = fmaf(sigmoidf_(xf3), softplusf_(xc3), s3);
    }
    *(float4*)&g_summed[n * FF + 4 * t] = make_float4(s0, s1, s2, s3);
}

// stats over g_summed (per column over atoms)
__global__ void __launch_bounds__(256) k_stat2() {
    int tid = threadIdx.x;
    int j = tid & 63;
    int grp = tid >> 6;
    float s = 0.f, s2 = 0.f;
    int nBase = blockIdx.x * 256 + grp * 64;
    for (int t = 0; t < 64; t++) {
        int n = nBase + t;
        if (n >= NA) break;
        float v = g_summed[n * FF + j];
        s += v;
        s2 = fmaf(v, v, s2);
    }
    atomicAdd(&g_stat2[j], (double)s);
    atomicAdd(&g_stat2[FF + j], (double)s2);
}

// BN affine params from accumulated stats.
__global__ void k_bnparam(int which,
                          const float* __restrict__ gamma,
                          const float* __restrict__ beta) {
    int j = threadIdx.x;
    if (which == 0) {
        if (j >= TWOF) return;
        double inv = 1.0 / (double)NM;
        double mu = g_stat1[j] * inv;
        double var = g_stat1[TWOF + j] * inv - mu * mu;
        float sc = gamma[j] * rsqrtf((float)var + 1e-5f);
        g_bn1[j] = sc;
        g_bn1[TWOF + j] = beta[j] - (float)mu * sc;
    } else {
        if (j >= FF) return;
        double inv = 1.0 / (double)NA;
        double mu = g_stat2[j] * inv;
        double var = g_stat2[FF + j] * inv - mu * mu;
        float sc = gamma[j] * rsqrtf((float)var + 1e-5f);
        g_bn2[j] = sc;
        g_bn2[FF + j] = beta[j] - (float)mu * sc;
    }
}

// h = softplus(h + bn2(summed))
__global__ void k_H() {
    int i = blockIdx.x * blockDim.x + threadIdx.x;
    if (i >= NA * FF) return;
    int j = i & 63;
    float x = fmaf(g_bn2[j], g_summed[i], g_bn2[FF + j]);
    g_h[i] = softplusf_(g_h[i] + x);
}

__global__ void k_zero_pool() {
    int i = blockIdx.x * 256 + threadIdx.x;
    if (i < BB * FF) g_pool[i] = 0.f;
    if (i < BB) g_cnt[i] = 0.f;
}

__global__ void k_pool(const int* __restrict__ cid) {
    int n = blockIdx.x;
    int c = cid[n];
    atomicAdd(&g_pool[c * FF + threadIdx.x], g_h[n * FF + threadIdx.x]);
    if (threadIdx.x == 0) atomicAdd(&g_cnt[c], 1.f);
}

// crys = pool/cnt; out[b] = softplus(crys@W_fc + b_fc) @ W_out + b_out
__global__ void k_head(const float* __restrict__ Wfc,
                       const float* __restrict__ bfc,
                       const float* __restrict__ Wout,
                       const float* __restrict__ bout,
                       float* __restrict__ out) {
    int b = blockIdx.x;
    int t = threadIdx.x;
    __shared__ float sc[FF];
    __shared__ float red[HH];
    float inv = 1.f / fmaxf(g_cnt[b], 1.f);
    if (t < FF) sc[t] = g_pool[b * FF + t] * inv;
    __syncthreads();
    float acc = bfc[t];
    #pragma unroll
    for (int k = 0; k < FF; k++) acc = fmaf(sc[k], __ldg(&Wfc[k * HH + t]), acc);
    red[t] = softplusf_(acc) * __ldg(&Wout[t]);
    __syncthreads();
    for (int off = 64; off > 0; off >>= 1) {
        if (t < off) red[t] += red[t + off];
        __syncthreads();
    }
    if (t == 0) out[b] = red[0] + bout[0];
}

// ---------------- launch ----------------
extern "C" void kernel_launch(void* const* d_in, const int* in_sizes, int n_in,
                              void* d_out, int out_size) {
    const float* atom_fea = (const float*)d_in[0];
    const float* nbr_fea  = (const float*)d_in[1];
    const int*   nbr_idx  = (const int*)d_in[2];
    const int*   cid      = (const int*)d_in[3];
    int o = (n_in >= 17 && in_sizes[4] == 1) ? 1 : 0;
    const float* W_emb = (const float*)d_in[4 + o];
    const float* b_emb = (const float*)d_in[5 + o];
    const float* Wf    = (const float*)d_in[6 + o];
    const float* bf    = (const float*)d_in[7 + o];
    const float* g1    = (const float*)d_in[8 + o];
    const float* b1    = (const float*)d_in[9 + o];
    const float* g2    = (const float*)d_in[10 + o];
    const float* b2    = (const float*)d_in[11 + o];
    const float* W_fc  = (const float*)d_in[12 + o];
    const float* b_fc  = (const float*)d_in[13 + o];
    const float* W_out = (const float*)d_in[14 + o];
    const float* b_out = (const float*)d_in[15 + o];
    float* out = (float*)d_out;

    k_embed<<<(NA + 63) / 64, 64>>>(atom_fea, W_emb, b_emb);

    for (int l = 0; l < NCONV; l++) {
        const float* Wfl = Wf + l * WF_STRIDE;
        const float* bfl = bf + l * TWOF;
        const float* g1l = g1 + l * TWOF;
        const float* b1l = b1 + l * TWOF;
        const float* g2l = g2 + l * FF;
        const float* b2l = b2 + l * FF;

        k_zero<<<1, 384>>>();
        k_AP<<<NA / 4, 128>>>(Wfl);
        k_G1<<<KG_GRID, 128>>>(nbr_fea, nbr_idx, Wfl, bfl);
        k_bnparam<<<1, 128>>>(0, g1l, b1l);
        k_S2<<<NA / 16, 256>>>();
        k_stat2<<<(NA + 255) / 256, 256>>>();
        k_bnparam<<<1, 64>>>(1, g2l, b2l);
        k_H<<<(NA * FF) / 256, 256>>>();
    }

    k_zero_pool<<<(BB * FF + 255) / 256, 256>>>();
    k_pool<<<NA, FF>>>(cid);
    k_head<<<BB, HH>>>(W_fc, b_fc, W_out, b_out, out);
}

// round 16
// speedup vs baseline: 1.1055x; 1.1055x over previous
#include <cuda_runtime.h>
#include <cuda_fp16.h>
#include <math.h>
#include <stdint.h>

// ---------------- problem dims (fixed by setup_inputs) ----------------
#define NA    100000      // atoms
#define MM    12          // neighbors per atom
#define ORIG  92          // input atom feature dim
#define NBRF  41          // neighbor (bond) feature dim
#define FF    64          // hidden feature dim
#define HH    128         // fc hidden
#define BB    2000        // crystals
#define NCONV 3
#define NM    (NA*MM)     // 1.2M edge rows
#define TWOF  (2*FF)      // 128
#define WF_ROWS (2*FF + NBRF)         // 169
#define WF_STRIDE (WF_ROWS * TWOF)    // 169*128 per layer

#define TILE_E  64                    // edges per GEMM tile
#define NTILES  (NM / TILE_E)         // 18750 exactly
#define KSTEPS  6                     // K=41 padded to 48 via zero B-frags
#define CSS     132                   // col-stride (halves) for C staging
#define NATILE  7                     // max atoms spanned by a 64-edge tile
#define KG_GRID 740                   // 148 SMs * 5
#define U_FLOATS (TILE_E * NBRF)      // 2624 (unpadded NF tile)
#define U_TAIL   8                    // zeroed guard floats after U

// ---------------- scratch (device globals; no allocation) -------------
__device__ float  g_h[NA * FF];                 // 25.6 MB
__device__ float  g_A[NA * TWOF];               // 51.2 MB  h @ Wf_self
__device__ __align__(16) __half g_Ph[NA * TWOF];   // 25.6 MB  h @ Wf_nbr (fp16)
__device__ __align__(16) __half g_Gh[NM * TWOF];   // 307 MB fp16 gated pre-BN
__device__ __align__(16) float g_summed[NA * FF];  // 25.6 MB
__device__ double g_stat1[2 * TWOF];            // sum / sumsq (128 cols)
__device__ double g_stat2[2 * FF];              // sum / sumsq (64 cols)
__device__ __align__(16) float g_bn1[2 * TWOF]; // scale(128), shift(128)
__device__ float  g_bn2[2 * FF];                // scale(64), shift(64)
__device__ float  g_pool[BB * FF];
__device__ float  g_cnt[BB];

// ---------------- helpers ----------------
__device__ __forceinline__ float softplusf_(float x) {
    return fmaxf(x, 0.f) + __logf(1.f + __expf(-fabsf(x)));
}
__device__ __forceinline__ float sigmoidf_(float x) {
    return 1.f / (1.f + __expf(-x));
}
__device__ __forceinline__ uint32_t f2tf32(float x) {
    uint32_t r;
    asm("cvt.rna.tf32.f32 %0, %1;" : "=r"(r) : "f"(x));
    return r;
}
#define MMA_TF32(c0,c1,c2,c3,a0,a1,a2,a3,b0,b1) \
    asm volatile("mma.sync.aligned.m16n8k8.row.col.f32.tf32.tf32.f32 " \
        "{%0,%1,%2,%3},{%4,%5,%6,%7},{%8,%9},{%0,%1,%2,%3};" \
        : "+f"(c0), "+f"(c1), "+f"(c2), "+f"(c3) \
        : "r"(a0), "r"(a1), "r"(a2), "r"(a3), "r"(b0), "r"(b1))

struct TileCtx {
    int tid, lane, warp, m0, r, cq;
};

// Pack B fragments as uint4 pairs; k rows >= NBRF are ZERO (this is what
// makes the unpadded-A out-of-row reads harmless: garbage * 0 = 0).
__device__ __forceinline__ void pack_B(uint4* Wp4, const float* __restrict__ Wf, int tid) {
    for (int i = tid; i < KSTEPS * 8 * 32; i += 128) {
        int ks  = i >> 8;
        int rem = i & 255;
        int ntp = rem >> 5;
        int ln  = rem & 31;
        int col0 = (2 * ntp) * 8 + (ln >> 2);
        int col1 = col0 + 8;
        int k0 = ks * 8 + (ln & 3);
        float w0 = (k0     < NBRF) ? __ldg(&Wf[(TWOF + k0    ) * TWOF + col0]) : 0.f;
        float w1 = (k0 + 4 < NBRF) ? __ldg(&Wf[(TWOF + k0 + 4) * TWOF + col0]) : 0.f;
        float w2 = (k0     < NBRF) ? __ldg(&Wf[(TWOF + k0    ) * TWOF + col1]) : 0.f;
        float w3 = (k0 + 4 < NBRF) ? __ldg(&Wf[(TWOF + k0 + 4) * TWOF + col1]) : 0.f;
        Wp4[i] = make_uint4(f2tf32(w0), f2tf32(w1), f2tf32(w2), f2tf32(w3));
    }
}

// NF staging = raw uint4 memcpy (no cvt, no pad). Tile is contiguous:
// 64*41 floats = 656 float4, 16B-aligned (e0*41*4 = t*10496, mult of 16).
// MMA consumes raw fp32 bits as tf32 (truncation rounding).
__device__ __forceinline__ void stage_NF(uint4* U4, const float* __restrict__ nbr_fea,
                                         int e0, int tid) {
    const uint4* src = (const uint4*)(nbr_fea + (size_t)e0 * NBRF);
    for (int i = tid; i < U_FLOATS / 4; i += 128) U4[i] = __ldg(&src[i]);
}

// stage A rows for the tile's atoms into smem as fp16
__device__ __forceinline__ void stage_A(__half* As_h, int n_first, int tid) {
    #pragma unroll
    for (int it = 0; it < NATILE; it++) {
        int n = n_first + it;
        if (n > NA - 1) n = NA - 1;
        As_h[it * TWOF + tid] = __float2half_rn(__ldg(&g_A[(size_t)n * TWOF + tid]));
    }
}

__device__ __forceinline__ void run_mma(float acc[16][4], const uint32_t* U,
                                        const uint4* Wp4, const TileCtx& c) {
    #pragma unroll
    for (int nt = 0; nt < 16; nt++)
        #pragma unroll
        for (int i = 0; i < 4; i++) acc[nt][i] = 0.f;
    #pragma unroll
    for (int ks = 0; ks < KSTEPS; ks++) {
        // unpadded row stride NBRF=41; k >= 41 reads spill into the next row
        // (finite NF data) or the zeroed tail — always multiplied by zero B.
        uint32_t a0 = U[(c.m0 + c.r    ) * NBRF + ks * 8 + c.cq    ];
        uint32_t a1 = U[(c.m0 + c.r + 8) * NBRF + ks * 8 + c.cq    ];
        uint32_t a2 = U[(c.m0 + c.r    ) * NBRF + ks * 8 + c.cq + 4];
        uint32_t a3 = U[(c.m0 + c.r + 8) * NBRF + ks * 8 + c.cq + 4];
        #pragma unroll
        for (int ntp = 0; ntp < 8; ntp++) {
            uint4 b = Wp4[(ks * 8 + ntp) * 32 + c.lane];
            MMA_TF32(acc[2*ntp  ][0], acc[2*ntp  ][1], acc[2*ntp  ][2], acc[2*ntp  ][3],
                     a0, a1, a2, a3, b.x, b.y);
            MMA_TF32(acc[2*ntp+1][0], acc[2*ntp+1][1], acc[2*ntp+1][2], acc[2*ntp+1][3],
                     a0, a1, a2, a3, b.z, b.w);
        }
    }
}

// stage C half-tile as fp16 (halves L1 bytes; spill is fp16 anyway)
__device__ __forceinline__ void stage_C(__half* Cs_h, const float acc[16][4],
                                        const TileCtx& c, int h) {
    if ((c.warp >> 1) == h) {
        int rl = c.m0 - h * 32 + c.r;
        #pragma unroll
        for (int nt = 0; nt < 16; nt++) {
            int jc = nt * 8 + 2 * c.cq;
            *(__half2*)&Cs_h[(rl    ) * CSS + jc] = __floats2half2_rn(acc[nt][0], acc[nt][1]);
            *(__half2*)&Cs_h[(rl + 8) * CSS + jc] = __floats2half2_rn(acc[nt][2], acc[nt][3]);
        }
    }
}

// ---------------- kernels ----------------

// h = atom_fea @ W_emb + b_emb    [NA,92]@[92,64]
// 16 rows per block, one sync (replaces the 64-phase serialized version).
__global__ void __launch_bounds__(128) k_embed(const float* __restrict__ atom,
                                               const float* __restrict__ W,
                                               const float* __restrict__ b) {
    __shared__ float sW[ORIG * FF];     // 23.5 KB
    __shared__ float sa[16 * ORIG];     // 5.9 KB
    __shared__ float sb[FF];
    int tid = threadIdx.x;
    for (int i = tid; i < ORIG * FF; i += 128) sW[i] = W[i];
    if (tid < FF) sb[tid] = b[tid];
    int r0 = blockIdx.x * 16;           // grid = NA/16 = 6250 exact
    for (int i = tid; i < 16 * ORIG; i += 128) sa[i] = atom[(size_t)r0 * ORIG + i];
    __syncthreads();
    int col = tid & 63;
    int rg  = tid >> 6;                 // 0/1 -> rows 8rg..8rg+7
    for (int rr = rg * 8; rr < rg * 8 + 8; rr++) {
        float acc = sb[col];
        #pragma unroll 4
        for (int k = 0; k < ORIG; k++)
            acc = fmaf(sa[rr * ORIG + k], sW[k * FF + col], acc);
        g_h[(r0 + rr) * FF + col] = acc;
    }
}

// A[n,j] = sum_k h[n,k] * Wf[k,j] (fp32);  P (fp16) = h @ Wf[64..128]
__global__ void __launch_bounds__(128) k_AP(const float* __restrict__ Wf) {
    __shared__ float sh[4][FF];
    int j = threadIdx.x;
    int n0 = blockIdx.x * 4;
    for (int i = j; i < 4 * FF; i += 128) {
        int r = i >> 6, k = i & 63;
        sh[r][k] = g_h[(n0 + r) * FF + k];
    }
    __syncthreads();
    float a0 = 0, a1 = 0, a2 = 0, a3 = 0;
    float p0 = 0, p1 = 0, p2 = 0, p3 = 0;
    #pragma unroll
    for (int k = 0; k < FF; k++) {
        float wa = __ldg(&Wf[k * TWOF + j]);
        float wb = __ldg(&Wf[(FF + k) * TWOF + j]);
        a0 = fmaf(sh[0][k], wa, a0); p0 = fmaf(sh[0][k], wb, p0);
        a1 = fmaf(sh[1][k], wa, a1); p1 = fmaf(sh[1][k], wb, p1);
        a2 = fmaf(sh[2][k], wa, a2); p2 = fmaf(sh[2][k], wb, p2);
        a3 = fmaf(sh[3][k], wa, a3); p3 = fmaf(sh[3][k], wb, p3);
    }
    g_A[(n0 + 0) * TWOF + j] = a0;  g_Ph[(n0 + 0) * TWOF + j] = __float2half_rn(p0);
    g_A[(n0 + 1) * TWOF + j] = a1;  g_Ph[(n0 + 1) * TWOF + j] = __float2half_rn(p1);
    g_A[(n0 + 2) * TWOF + j] = a2;  g_Ph[(n0 + 2) * TWOF + j] = __float2half_rn(p2);
    g_A[(n0 + 3) * TWOF + j] = a3;  g_Ph[(n0 + 3) * TWOF + j] = __float2half_rn(p3);
}

// zero the stat accumulators only
__global__ void k_zero() {
    int i = threadIdx.x;
    if (i < 2 * TWOF) g_stat1[i] = 0.0;
    if (i < 2 * FF)   g_stat2[i] = 0.0;
}

// ---------------------------------------------------------------------
// Pass 1: k_G1 — tf32 GEMM + A(fp16 smem)/P(fp16 LDG.64) gather + bias ->
// column stats (fp32 accum -> fp64 atomic) + fp16 spill of G.
// ---------------------------------------------------------------------
__global__ void __launch_bounds__(128, 5) k_G1(const float* __restrict__ nbr_fea,
                                               const int*   __restrict__ idx,
                                               const float* __restrict__ Wf,
                                               const float* __restrict__ bf) {
    __shared__ uint4 Wp4[KSTEPS * 8 * 32];            // 24.0 KB
    __shared__ __align__(16) char UC[(U_FLOATS + U_TAIL) * 4];  // 10.5 KB (U | Cs_h)
    __shared__ __align__(16) __half As_h[NATILE * TWOF];        // 1.75 KB
    __shared__ int sidx[TILE_E];
    uint32_t* U   = (uint32_t*)UC;
    uint4*   U4   = (uint4*)UC;
    __half*  Cs_h = (__half*)UC;        // 32*CSS halves = 8448 B < 10496 B (tail safe)

    TileCtx c;
    c.tid = threadIdx.x; c.lane = c.tid & 31; c.warp = c.tid >> 5;
    c.m0 = c.warp * 16; c.r = c.lane >> 2; c.cq = c.lane & 3;
    int tid = c.tid;

    pack_B(Wp4, Wf, tid);
    if (tid < U_TAIL) U[U_FLOATS + tid] = 0;   // NaN-guard for row-63 OOB k reads

    int jq = tid & 31;           // column quad: cols 4jq..4jq+3
    int g  = tid >> 5;           // edge subgroup (8 edges) within 32-half
    float4 bf4 = __ldg((const float4*)&bf[4 * jq]);

    float ds0 = 0, ds1 = 0, ds2 = 0, ds3 = 0;
    float dq0 = 0, dq1 = 0, dq2 = 0, dq3 = 0;

    for (int t = blockIdx.x; t < NTILES; t += gridDim.x) {
        int e0 = t * TILE_E;
        int n_first = e0 / MM;
        __syncthreads();
        stage_NF(U4, nbr_fea, e0, tid);
        stage_A(As_h, n_first, tid);
        if (tid < TILE_E) sidx[tid] = idx[e0 + tid];
        __syncthreads();

        float acc[16][4];
        run_mma(acc, U, Wp4, c);
        __syncthreads();

        #pragma unroll
        for (int h = 0; h < 2; h++) {
            stage_C(Cs_h, acc, c, h);
            __syncthreads();
            int eg = e0 + h * 32 + g * 8;
            int n  = eg / MM;
            int rem = eg - n * MM;
            int nl  = n - n_first;
            float ts0 = 0, ts1 = 0, ts2 = 0, ts3 = 0;
            float tq0 = 0, tq1 = 0, tq2 = 0, tq3 = 0;
            #pragma unroll
            for (int i = 0; i < 8; i++) {
                int le = g * 8 + i;
                int nb = sidx[h * 32 + le];
                uint2 pu = __ldg((const uint2*)&g_Ph[(size_t)nb * TWOF + 4 * jq]);
                uint2 au = *(const uint2*)&As_h[nl * TWOF + 4 * jq];
                uint2 cu = *(const uint2*)&Cs_h[le * CSS + 4 * jq];
                float2 p01 = __half22float2(*reinterpret_cast<__half2*>(&pu.x));
                float2 p23 = __half22float2(*reinterpret_cast<__half2*>(&pu.y));
                float2 a01 = __half22float2(*reinterpret_cast<__half2*>(&au.x));
                float2 a23 = __half22float2(*reinterpret_cast<__half2*>(&au.y));
                float2 c01 = __half22float2(*reinterpret_cast<__half2*>(&cu.x));
                float2 c23 = __half22float2(*reinterpret_cast<__half2*>(&cu.y));
                float v0 = c01.x + a01.x + p01.x + bf4.x;
                float v1 = c01.y + a01.y + p01.y + bf4.y;
                float v2 = c23.x + a23.x + p23.x + bf4.z;
                float v3 = c23.y + a23.y + p23.y + bf4.w;
                ts0 += v0; tq0 = fmaf(v0, v0, tq0);
                ts1 += v1; tq1 = fmaf(v1, v1, tq1);
                ts2 += v2; tq2 = fmaf(v2, v2, tq2);
                ts3 += v3; tq3 = fmaf(v3, v3, tq3);
                {
                    __half2 ha = __floats2half2_rn(v0, v1);
                    __half2 hb = __floats2half2_rn(v2, v3);
                    uint2 u;
                    u.x = *reinterpret_cast<unsigned*>(&ha);
                    u.y = *reinterpret_cast<unsigned*>(&hb);
                    *reinterpret_cast<uint2*>(&g_Gh[(size_t)(eg + i) * TWOF + 4 * jq]) = u;
                }
                if (++rem == MM) { rem = 0; nl++; }
            }
            ds0 += ts0; ds1 += ts1; ds2 += ts2; ds3 += ts3;
            dq0 += tq0; dq1 += tq1; dq2 += tq2; dq3 += tq3;
            __syncthreads();
        }
    }

    atomicAdd(&g_stat1[4 * jq + 0], (double)ds0);
    atomicAdd(&g_stat1[4 * jq + 1], (double)ds1);
    atomicAdd(&g_stat1[4 * jq + 2], (double)ds2);
    atomicAdd(&g_stat1[4 * jq + 3], (double)ds3);
    atomicAdd(&g_stat1[TWOF + 4 * jq + 0], (double)dq0);
    atomicAdd(&g_stat1[TWOF + 4 * jq + 1], (double)dq1);
    atomicAdd(&g_stat1[TWOF + 4 * jq + 2], (double)dq2);
    atomicAdd(&g_stat1[TWOF + 4 * jq + 3], (double)dq3);
}

// ---------------------------------------------------------------------
// Pass 2: k_S2 — stream fp16 G, bn1 + sigmoid*softplus, per-atom reduce,
// DIRECT store to g_summed. 256 thr = 16 atoms x 16 col-quads.
// ---------------------------------------------------------------------
__global__ void __launch_bounds__(256) k_S2() {
    int tid = threadIdx.x;
    int t = tid & 15;
    int a = tid >> 4;
    int n = blockIdx.x * 16 + a;      // grid = NA/16 = 6250 exact

    float4 scf = *(const float4*)&g_bn1[4 * t];
    float4 scc = *(const float4*)&g_bn1[FF + 4 * t];
    float4 shf = *(const float4*)&g_bn1[TWOF + 4 * t];
    float4 shc = *(const float4*)&g_bn1[TWOF + FF + 4 * t];

    size_t base = (size_t)n * MM * TWOF;
    float s0 = 0, s1 = 0, s2 = 0, s3 = 0;
    #pragma unroll
    for (int m = 0; m < MM; m++) {
        uint2 uf = __ldg((const uint2*)&g_Gh[base + m * TWOF + 4 * t]);
        uint2 uc = __ldg((const uint2*)&g_Gh[base + m * TWOF + FF + 4 * t]);
        float2 f01 = __half22float2(*reinterpret_cast<__half2*>(&uf.x));
        float2 f23 = __half22float2(*reinterpret_cast<__half2*>(&uf.y));
        float2 c01 = __half22float2(*reinterpret_cast<__half2*>(&uc.x));
        float2 c23 = __half22float2(*reinterpret_cast<__half2*>(&uc.y));
        float xf0 = fmaf(scf.x, f01.x, shf.x);
        float xf1 = fmaf(scf.y, f01.y, shf.y);
        float xf2 = fmaf(scf.z, f23.x, shf.z);
        float xf3 = fmaf(scf.w, f23.y, shf.w);
        float xc0 = fmaf(scc.x, c01.x, shc.x);
        float xc1 = fmaf(scc.y, c01.y, shc.y);
        float xc2 = fmaf(scc.z, c23.x, shc.z);
        float xc3 = fmaf(scc.w, c23.y, shc.w);
        s0 = fmaf(sigmoidf_(xf0), softplusf_(xc0), s0);
        s1 = fmaf(sigmoidf_(xf1), softplusf_(xc1), s1);
        s2 = fmaf(sigmoidf_(xf2), softplusf_(xc2), s2);
        s3 = fmaf(sigmoidf_(xf3), softplusf_(xc3), s3);
    }
    *(float4*)&g_summed[n * FF + 4 * t] = make_float4(s0, s1, s2, s3);
}

// stats over g_summed (per column over atoms)
__global__ void __launch_bounds__(256) k_stat2() {
    int tid = threadIdx.x;
    int j = tid & 63;
    int grp = tid >> 6;
    float s = 0.f, s2 = 0.f;
    int nBase = blockIdx.x * 256 + grp * 64;
    for (int t = 0; t < 64; t++) {
        int n = nBase + t;
        if (n >= NA) break;
        float v = g_summed[n * FF + j];
        s += v;
        s2 = fmaf(v, v, s2);
    }
    atomicAdd(&g_stat2[j], (double)s);
    atomicAdd(&g_stat2[FF + j], (double)s2);
}

// BN affine params from accumulated stats.
__global__ void k_bnparam(int which,
                          const float* __restrict__ gamma,
                          const float* __restrict__ beta) {
    int j = threadIdx.x;
    if (which == 0) {
        if (j >= TWOF) return;
        double inv = 1.0 / (double)NM;
        double mu = g_stat1[j] * inv;
        double var = g_stat1[TWOF + j] * inv - mu * mu;
        float sc = gamma[j] * rsqrtf((float)var + 1e-5f);
        g_bn1[j] = sc;
        g_bn1[TWOF + j] = beta[j] - (float)mu * sc;
    } else {
        if (j >= FF) return;
        double inv = 1.0 / (double)NA;
        double mu = g_stat2[j] * inv;
        double var = g_stat2[FF + j] * inv - mu * mu;
        float sc = gamma[j] * rsqrtf((float)var + 1e-5f);
        g_bn2[j] = sc;
        g_bn2[FF + j] = beta[j] - (float)mu * sc;
    }
}

// h = softplus(h + bn2(summed))
__global__ void k_H() {
    int i = blockIdx.x * blockDim.x + threadIdx.x;
    if (i >= NA * FF) return;
    int j = i & 63;
    float x = fmaf(g_bn2[j], g_summed[i], g_bn2[FF + j]);
    g_h[i] = softplusf_(g_h[i] + x);
}

__global__ void k_zero_pool() {
    int i = blockIdx.x * 256 + threadIdx.x;
    if (i < BB * FF) g_pool[i] = 0.f;
    if (i < BB) g_cnt[i] = 0.f;
}

__global__ void k_pool(const int* __restrict__ cid) {
    int n = blockIdx.x;
    int c = cid[n];
    atomicAdd(&g_pool[c * FF + threadIdx.x], g_h[n * FF + threadIdx.x]);
    if (threadIdx.x == 0) atomicAdd(&g_cnt[c], 1.f);
}

// crys = pool/cnt; out[b] = softplus(crys@W_fc + b_fc) @ W_out + b_out
__global__ void k_head(const float* __restrict__ Wfc,
                       const float* __restrict__ bfc,
                       const float* __restrict__ Wout,
                       const float* __restrict__ bout,
                       float* __restrict__ out) {
    int b = blockIdx.x;
    int t = threadIdx.x;
    __shared__ float sc[FF];
    __shared__ float red[HH];
    float inv = 1.f / fmaxf(g_cnt[b], 1.f);
    if (t < FF) sc[t] = g_pool[b * FF + t] * inv;
    __syncthreads();
    float acc = bfc[t];
    #pragma unroll
    for (int k = 0; k < FF; k++) acc = fmaf(sc[k], __ldg(&Wfc[k * HH + t]), acc);
    red[t] = softplusf_(acc) * __ldg(&Wout[t]);
    __syncthreads();
    for (int off = 64; off > 0; off >>= 1) {
        if (t < off) red[t] += red[t + off];
        __syncthreads();
    }
    if (t == 0) out[b] = red[0] + bout[0];
}

// ---------------- launch ----------------
extern "C" void kernel_launch(void* const* d_in, const int* in_sizes, int n_in,
                              void* d_out, int out_size) {
    const float* atom_fea = (const float*)d_in[0];
    const float* nbr_fea  = (const float*)d_in[1];
    const int*   nbr_idx  = (const int*)d_in[2];
    const int*   cid      = (const int*)d_in[3];
    int o = (n_in >= 17 && in_sizes[4] == 1) ? 1 : 0;
    const float* W_emb = (const float*)d_in[4 + o];
    const float* b_emb = (const float*)d_in[5 + o];
    const float* Wf    = (const float*)d_in[6 + o];
    const float* bf    = (const float*)d_in[7 + o];
    const float* g1    = (const float*)d_in[8 + o];
    const float* b1    = (const float*)d_in[9 + o];
    const float* g2    = (const float*)d_in[10 + o];
    const float* b2    = (const float*)d_in[11 + o];
    const float* W_fc  = (const float*)d_in[12 + o];
    const float* b_fc  = (const float*)d_in[13 + o];
    const float* W_out = (const float*)d_in[14 + o];
    const float* b_out = (const float*)d_in[15 + o];
    float* out = (float*)d_out;

    k_embed<<<NA / 16, 128>>>(atom_fea, W_emb, b_emb);

    for (int l = 0; l < NCONV; l++) {
        const float* Wfl = Wf + l * WF_STRIDE;
        const float* bfl = bf + l * TWOF;
        const float* g1l = g1 + l * TWOF;
        const float* b1l = b1 + l * TWOF;
        const float* g2l = g2 + l * FF;
        const float* b2l = b2 + l * FF;

        k_zero<<<1, 384>>>();
        k_AP<<<NA / 4, 128>>>(Wfl);
        k_G1<<<KG_GRID, 128>>>(nbr_fea, nbr_idx, Wfl, bfl);
        k_bnparam<<<1, 128>>>(0, g1l, b1l);
        k_S2<<<NA / 16, 256>>>();
        k_stat2<<<(NA + 255) / 256, 256>>>();
        k_bnparam<<<1, 64>>>(1, g2l, b2l);
        k_H<<<(NA * FF) / 256, 256>>>();
    }

    k_zero_pool<<<(BB * FF + 255) / 256, 256>>>();
    k_pool<<<NA, FF>>>(cid);
    k_head<<<BB, HH>>>(W_fc, b_fc, W_out, b_out, out);
}